// round 1
// baseline (speedup 1.0000x reference)
#include <cuda_runtime.h>

#define N_NODES 100000
#define N_EDGES 3200000
#define HID 32
#define INCH 128
#define LN_EPS 1e-5f
#define NB_SCAN ((N_NODES + 1023) / 1024)   // 98 scan blocks

// ---------------- static scratch (no dynamic allocation allowed) ------------
__device__ float d_y[N_NODES * HID];      // scaled GEMM output  y = s * (h @ W)
__device__ float d_h[N_NODES * HID];      // post-LN/ReLU activations
__device__ float d_y3[N_NODES * 2];       // layer-3 scaled GEMM output
__device__ float d_s[N_NODES];            // rsqrt(deg+1)
__device__ int   d_cnt[N_NODES];          // in-degree counts
__device__ int   d_rowptr[N_NODES + 1];   // CSR row pointers (by dst)
__device__ int   d_cur[N_NODES];          // fill cursors
__device__ int   d_csr[N_EDGES];          // CSR: src ids grouped by dst
__device__ int   d_blocksum[128];
__device__ int   d_blockoff[128];

// ---------------- degree count ----------------------------------------------
__global__ void k_zero_cnt() {
    int i = blockIdx.x * blockDim.x + threadIdx.x;
    if (i < N_NODES) d_cnt[i] = 0;
}

__global__ void k_count(const int* __restrict__ dst) {
    int e = blockIdx.x * blockDim.x + threadIdx.x;
    if (e < N_EDGES) atomicAdd(&d_cnt[dst[e]], 1);
}

// ---------------- 3-kernel exclusive scan of d_cnt -> d_rowptr --------------
__global__ void k_scan_a() {
    __shared__ int sh[1024];
    int t = threadIdx.x;
    int i = blockIdx.x * 1024 + t;
    int v = (i < N_NODES) ? d_cnt[i] : 0;
    sh[t] = v;
    __syncthreads();
    #pragma unroll
    for (int off = 1; off < 1024; off <<= 1) {
        int u = (t >= off) ? sh[t - off] : 0;
        __syncthreads();
        sh[t] += u;
        __syncthreads();
    }
    if (i < N_NODES) d_rowptr[i] = sh[t] - v;       // local exclusive
    if (t == 1023) d_blocksum[blockIdx.x] = sh[1023];
}

__global__ void k_scan_b() {
    __shared__ int sh[128];
    int t = threadIdx.x;
    int v = (t < NB_SCAN) ? d_blocksum[t] : 0;
    sh[t] = v;
    __syncthreads();
    #pragma unroll
    for (int off = 1; off < 128; off <<= 1) {
        int u = (t >= off) ? sh[t - off] : 0;
        __syncthreads();
        sh[t] += u;
        __syncthreads();
    }
    if (t < NB_SCAN) d_blockoff[t] = sh[t] - v;     // exclusive block offsets
}

__global__ void k_scan_c() {
    int i = blockIdx.x * blockDim.x + threadIdx.x;
    if (i < N_NODES) {
        int rp = d_rowptr[i] + d_blockoff[i >> 10];
        d_rowptr[i] = rp;
        d_cur[i]    = rp;
        d_s[i]      = rsqrtf((float)d_cnt[i] + 1.0f);
    }
    if (i == 0) d_rowptr[N_NODES] = N_EDGES;
}

__global__ void k_fill(const int* __restrict__ src, const int* __restrict__ dst) {
    int e = blockIdx.x * blockDim.x + threadIdx.x;
    if (e < N_EDGES) {
        int d   = dst[e];
        int pos = atomicAdd(&d_cur[d], 1);
        d_csr[pos] = src[e];
    }
}

// ---------------- GEMM: y = s * (h @ W), W is [INC,32] row-major ------------
template <int INC>
__global__ void k_gemm(const float* __restrict__ h, const float* __restrict__ W,
                       float* __restrict__ yout) {
    __shared__ float Ws[INC * 32];
    for (int i = threadIdx.x; i < INC * 32; i += blockDim.x) Ws[i] = W[i];
    __syncthreads();

    int node = blockIdx.x * blockDim.x + threadIdx.x;
    if (node >= N_NODES) return;

    float acc[32];
    #pragma unroll
    for (int j = 0; j < 32; j++) acc[j] = 0.0f;

    const float4* hr = (const float4*)(h + (size_t)node * INC);
    #pragma unroll 4
    for (int k4 = 0; k4 < INC / 4; k4++) {
        float4 xv = hr[k4];
        const float* w0 = &Ws[(4 * k4 + 0) * 32];
        const float* w1 = &Ws[(4 * k4 + 1) * 32];
        const float* w2 = &Ws[(4 * k4 + 2) * 32];
        const float* w3 = &Ws[(4 * k4 + 3) * 32];
        #pragma unroll
        for (int j = 0; j < 32; j++) {
            acc[j] += xv.x * w0[j] + xv.y * w1[j] + xv.z * w2[j] + xv.w * w3[j];
        }
    }

    float sv = d_s[node];
    float4* yo = (float4*)(yout + (size_t)node * 32);
    #pragma unroll
    for (int j4 = 0; j4 < 8; j4++) {
        float4 r;
        r.x = acc[4 * j4 + 0] * sv;
        r.y = acc[4 * j4 + 1] * sv;
        r.z = acc[4 * j4 + 2] * sv;
        r.w = acc[4 * j4 + 3] * sv;
        yo[j4] = r;
    }
}

// ---------------- layer-3 GEMM: y3 = s * (h @ W3), W3 is [32,2] -------------
__global__ void k_gemm_out(const float* __restrict__ h, const float* __restrict__ W3,
                           float* __restrict__ y3) {
    __shared__ float Ws[64];
    if (threadIdx.x < 64) Ws[threadIdx.x] = W3[threadIdx.x];
    __syncthreads();

    int node = blockIdx.x * blockDim.x + threadIdx.x;
    if (node >= N_NODES) return;

    const float4* hr = (const float4*)(h + (size_t)node * 32);
    float a0 = 0.0f, a1 = 0.0f;
    #pragma unroll
    for (int k4 = 0; k4 < 8; k4++) {
        float4 v = hr[k4];
        a0 += v.x * Ws[(4 * k4 + 0) * 2 + 0] + v.y * Ws[(4 * k4 + 1) * 2 + 0]
            + v.z * Ws[(4 * k4 + 2) * 2 + 0] + v.w * Ws[(4 * k4 + 3) * 2 + 0];
        a1 += v.x * Ws[(4 * k4 + 0) * 2 + 1] + v.y * Ws[(4 * k4 + 1) * 2 + 1]
            + v.z * Ws[(4 * k4 + 2) * 2 + 1] + v.w * Ws[(4 * k4 + 3) * 2 + 1];
    }
    float sv = d_s[node];
    float2 r; r.x = a0 * sv; r.y = a1 * sv;
    *(float2*)(y3 + (size_t)node * 2) = r;
}

// ---------------- aggregate (32-wide) + bias + [LN + ReLU] ------------------
// warp = 4 nodes, 8 lanes/node, float4 per lane (4 channels).
template <bool DO_LN>
__global__ void k_agg(const float* __restrict__ y, float* __restrict__ out,
                      const float* __restrict__ bias, const float* __restrict__ g,
                      const float* __restrict__ be) {
    int tid  = blockIdx.x * blockDim.x + threadIdx.x;
    int node = tid >> 3;
    int c4   = tid & 7;
    if (node >= N_NODES) return;

    int lo = d_rowptr[node];
    int hi = d_rowptr[node + 1];

    // self-loop contribution
    float4 acc = *(const float4*)(y + (size_t)node * 32 + c4 * 4);

    int e = lo;
    for (; e + 1 < hi; e += 2) {
        int s0 = __ldg(&d_csr[e]);
        int s1 = __ldg(&d_csr[e + 1]);
        float4 v0 = *(const float4*)(y + (size_t)s0 * 32 + c4 * 4);
        float4 v1 = *(const float4*)(y + (size_t)s1 * 32 + c4 * 4);
        acc.x += v0.x + v1.x;
        acc.y += v0.y + v1.y;
        acc.z += v0.z + v1.z;
        acc.w += v0.w + v1.w;
    }
    if (e < hi) {
        int s0 = __ldg(&d_csr[e]);
        float4 v0 = *(const float4*)(y + (size_t)s0 * 32 + c4 * 4);
        acc.x += v0.x; acc.y += v0.y; acc.z += v0.z; acc.w += v0.w;
    }

    float sv = d_s[node];
    float4 bv = *(const float4*)(bias + c4 * 4);
    acc.x = acc.x * sv + bv.x;
    acc.y = acc.y * sv + bv.y;
    acc.z = acc.z * sv + bv.z;
    acc.w = acc.w * sv + bv.w;

    if (DO_LN) {
        float sum = acc.x + acc.y + acc.z + acc.w;
        sum += __shfl_xor_sync(0xffffffffu, sum, 1);
        sum += __shfl_xor_sync(0xffffffffu, sum, 2);
        sum += __shfl_xor_sync(0xffffffffu, sum, 4);
        float mu = sum * (1.0f / 32.0f);

        float dx = acc.x - mu, dy = acc.y - mu, dz = acc.z - mu, dw = acc.w - mu;
        float vs = dx * dx + dy * dy + dz * dz + dw * dw;
        vs += __shfl_xor_sync(0xffffffffu, vs, 1);
        vs += __shfl_xor_sync(0xffffffffu, vs, 2);
        vs += __shfl_xor_sync(0xffffffffu, vs, 4);
        float rinv = rsqrtf(vs * (1.0f / 32.0f) + LN_EPS);

        float4 gv  = *(const float4*)(g  + c4 * 4);
        float4 bev = *(const float4*)(be + c4 * 4);
        acc.x = fmaxf(dx * rinv * gv.x + bev.x, 0.0f);
        acc.y = fmaxf(dy * rinv * gv.y + bev.y, 0.0f);
        acc.z = fmaxf(dz * rinv * gv.z + bev.z, 0.0f);
        acc.w = fmaxf(dw * rinv * gv.w + bev.w, 0.0f);
    }

    *(float4*)(out + (size_t)node * 32 + c4 * 4) = acc;
}

// ---------------- final 2-wide aggregate -> logits --------------------------
__global__ void k_agg2(const float* __restrict__ y3, float* __restrict__ out,
                       const float* __restrict__ b3) {
    int node = blockIdx.x * blockDim.x + threadIdx.x;
    if (node >= N_NODES) return;

    int lo = d_rowptr[node];
    int hi = d_rowptr[node + 1];

    float2 acc = *(const float2*)(y3 + (size_t)node * 2);
    int e = lo;
    for (; e + 1 < hi; e += 2) {
        int s0 = __ldg(&d_csr[e]);
        int s1 = __ldg(&d_csr[e + 1]);
        float2 v0 = *(const float2*)(y3 + (size_t)s0 * 2);
        float2 v1 = *(const float2*)(y3 + (size_t)s1 * 2);
        acc.x += v0.x + v1.x;
        acc.y += v0.y + v1.y;
    }
    if (e < hi) {
        int s0 = __ldg(&d_csr[e]);
        float2 v0 = *(const float2*)(y3 + (size_t)s0 * 2);
        acc.x += v0.x; acc.y += v0.y;
    }

    float sv = d_s[node];
    float2 r;
    r.x = acc.x * sv + b3[0];
    r.y = acc.y * sv + b3[1];
    *(float2*)(out + (size_t)node * 2) = r;
}

// ---------------- launch ----------------------------------------------------
extern "C" void kernel_launch(void* const* d_in, const int* in_sizes, int n_in,
                              void* d_out, int out_size) {
    const float* x   = (const float*)d_in[0];
    const int*   ei  = (const int*)d_in[1];
    const float* W1  = (const float*)d_in[2];
    const float* b1  = (const float*)d_in[3];
    const float* g1  = (const float*)d_in[4];
    const float* be1 = (const float*)d_in[5];
    const float* W2  = (const float*)d_in[6];
    const float* b2  = (const float*)d_in[7];
    const float* g2  = (const float*)d_in[8];
    const float* be2 = (const float*)d_in[9];
    const float* W3  = (const float*)d_in[10];
    const float* b3  = (const float*)d_in[11];
    float* out = (float*)d_out;

    const int* src = ei;
    const int* dst = ei + N_EDGES;

    float* yp;  cudaGetSymbolAddress((void**)&yp,  d_y);
    float* hp;  cudaGetSymbolAddress((void**)&hp,  d_h);
    float* y3p; cudaGetSymbolAddress((void**)&y3p, d_y3);

    const int TB = 256;
    const int gN = (N_NODES + TB - 1) / TB;     // 391
    const int gE = (N_EDGES + TB - 1) / TB;     // 12500
    const int gA = (N_NODES * 8 + TB - 1) / TB; // 3125

    // graph preprocessing: degrees, CSR
    k_zero_cnt<<<gN, TB>>>();
    k_count<<<gE, TB>>>(dst);
    k_scan_a<<<NB_SCAN, 1024>>>();
    k_scan_b<<<1, 128>>>();
    k_scan_c<<<gN, TB>>>();
    k_fill<<<gE, TB>>>(src, dst);

    // layer 1: 128 -> 32, LN + ReLU
    k_gemm<INCH><<<gN, TB>>>(x, W1, yp);
    k_agg<true><<<gA, TB>>>(yp, hp, b1, g1, be1);

    // layer 2: 32 -> 32, LN + ReLU
    k_gemm<HID><<<gN, TB>>>(hp, W2, yp);
    k_agg<true><<<gA, TB>>>(yp, hp, b2, g2, be2);

    // layer 3: 32 -> 2
    k_gemm_out<<<gN, TB>>>(hp, W3, y3p);
    k_agg2<<<gN, TB>>>(y3p, out, b3);
}

// round 2
// speedup vs baseline: 1.1117x; 1.1117x over previous
#include <cuda_runtime.h>
#include <cuda_fp16.h>

#define N_NODES 100000
#define N_EDGES 3200000
#define LN_EPS 1e-5f
#define NB_SCAN ((N_NODES + 1023) / 1024)   // 98 scan blocks

typedef unsigned long long ull;

// ---------------- static scratch ---------------------------------------------
__device__ __half d_y1[N_NODES * 32];     // fp16 scaled feature buffer, layer 1
__device__ __half d_y2[N_NODES * 32];     // fp16 scaled feature buffer, layer 2
__device__ float  d_y3[N_NODES * 2];      // layer-3 scaled GEMM output (fp32)
__device__ float  d_s[N_NODES];           // rsqrt(deg+1)
__device__ int    d_cnt[N_NODES];
__device__ int    d_rowptr[N_NODES + 1];
__device__ int    d_cur[N_NODES];
__device__ int    d_csr[N_EDGES];
__device__ int    d_blocksum[128];
__device__ int    d_blockoff[128];

// ---------------- f32x2 helpers (Blackwell packed fp32) ----------------------
__device__ __forceinline__ ull pack2(float x) {
    ull r; asm("mov.b64 %0, {%1, %1};" : "=l"(r) : "f"(x)); return r;
}
__device__ __forceinline__ void fma2(ull& d, ull a, ull b) {
    asm("fma.rn.f32x2 %0, %1, %2, %0;" : "+l"(d) : "l"(a), "l"(b));
}
__device__ __forceinline__ float2 unpack2(ull v) {
    float lo, hi; asm("mov.b64 {%0, %1}, %2;" : "=f"(lo), "=f"(hi) : "l"(v));
    return make_float2(lo, hi);
}
__device__ __forceinline__ float4 h4load(const __half* p) {
    uint2 u = *(const uint2*)p;
    __half2 a = *(__half2*)&u.x;
    __half2 b = *(__half2*)&u.y;
    float2 fa = __half22float2(a), fb = __half22float2(b);
    return make_float4(fa.x, fa.y, fb.x, fb.y);
}

// ---------------- degree count -----------------------------------------------
__global__ void k_count(const int* __restrict__ dst) {
    int e = blockIdx.x * blockDim.x + threadIdx.x;
    if (e < N_EDGES) atomicAdd(&d_cnt[dst[e]], 1);
}

// ---------------- 3-kernel exclusive scan ------------------------------------
__global__ void k_scan_a() {
    __shared__ int sh[1024];
    int t = threadIdx.x;
    int i = blockIdx.x * 1024 + t;
    int v = (i < N_NODES) ? d_cnt[i] : 0;
    sh[t] = v;
    __syncthreads();
    #pragma unroll
    for (int off = 1; off < 1024; off <<= 1) {
        int u = (t >= off) ? sh[t - off] : 0;
        __syncthreads();
        sh[t] += u;
        __syncthreads();
    }
    if (i < N_NODES) d_rowptr[i] = sh[t] - v;
    if (t == 1023) d_blocksum[blockIdx.x] = sh[1023];
}

__global__ void k_scan_b() {
    __shared__ int sh[128];
    int t = threadIdx.x;
    int v = (t < NB_SCAN) ? d_blocksum[t] : 0;
    sh[t] = v;
    __syncthreads();
    #pragma unroll
    for (int off = 1; off < 128; off <<= 1) {
        int u = (t >= off) ? sh[t - off] : 0;
        __syncthreads();
        sh[t] += u;
        __syncthreads();
    }
    if (t < NB_SCAN) d_blockoff[t] = sh[t] - v;
}

__global__ void k_scan_c() {
    int i = blockIdx.x * blockDim.x + threadIdx.x;
    if (i < N_NODES) {
        int rp = d_rowptr[i] + d_blockoff[i >> 10];
        d_rowptr[i] = rp;
        d_cur[i]    = rp;
        d_s[i]      = rsqrtf((float)d_cnt[i] + 1.0f);
    }
    if (i == 0) d_rowptr[N_NODES] = N_EDGES;
}

__global__ void k_fill(const int* __restrict__ src, const int* __restrict__ dst) {
    int e = blockIdx.x * blockDim.x + threadIdx.x;
    if (e < N_EDGES) {
        int d   = dst[e];
        int pos = atomicAdd(&d_cur[d], 1);
        d_csr[pos] = src[e];
    }
}

// ---------------- gemm1: y1 = fp16( s * (x @ W1) ), 128 -> 32 ----------------
// Block: 256 threads, 256 nodes. Thread = 4 nodes (ng) x 8 channels (cg),
// channel-pair f32x2 accumulators. x staged in smem in 16-k chunks.
__global__ __launch_bounds__(256) void k_gemm1(const float* __restrict__ x,
                                               const float* __restrict__ W,
                                               __half* __restrict__ y) {
    __shared__ float shw[128 * 32];     // 16 KB
    __shared__ float shx[256 * 17];     // 17 KB (stride-17 pad)
    int t  = threadIdx.x;
    int cg = t & 3;        // channels cg*8 .. cg*8+7
    int ng = t >> 2;       // nodes ng*4 .. ng*4+3 (local)
    int nb = blockIdx.x * 256;

    for (int i = t; i < 128 * 32; i += 256) shw[i] = W[i];

    ull acc[4][4];
    #pragma unroll
    for (int ni = 0; ni < 4; ni++)
        #pragma unroll
        for (int j = 0; j < 4; j++) acc[ni][j] = 0ull;

    for (int kc = 0; kc < 8; kc++) {
        __syncthreads();
        #pragma unroll
        for (int i = 0; i < 4; i++) {
            int lin = t + i * 256;            // 0..1023 float4 slots
            int n = lin >> 2, k4 = lin & 3;
            float4 v = make_float4(0.f, 0.f, 0.f, 0.f);
            if (nb + n < N_NODES)
                v = *(const float4*)(x + (size_t)(nb + n) * 128 + kc * 16 + k4 * 4);
            float* p = &shx[n * 17 + k4 * 4];
            p[0] = v.x; p[1] = v.y; p[2] = v.z; p[3] = v.w;
        }
        __syncthreads();
        #pragma unroll
        for (int k = 0; k < 16; k++) {
            const ull* wp = (const ull*)&shw[(kc * 16 + k) * 32 + cg * 8];
            ull w0 = wp[0], w1 = wp[1], w2 = wp[2], w3 = wp[3];
            #pragma unroll
            for (int ni = 0; ni < 4; ni++) {
                ull a = pack2(shx[(ng * 4 + ni) * 17 + k]);
                fma2(acc[ni][0], a, w0);
                fma2(acc[ni][1], a, w1);
                fma2(acc[ni][2], a, w2);
                fma2(acc[ni][3], a, w3);
            }
        }
    }

    #pragma unroll
    for (int ni = 0; ni < 4; ni++) {
        int n = nb + ng * 4 + ni;
        if (n < N_NODES) {
            float sv = d_s[n];
            float2 p0 = unpack2(acc[ni][0]);
            float2 p1 = unpack2(acc[ni][1]);
            float2 p2 = unpack2(acc[ni][2]);
            float2 p3 = unpack2(acc[ni][3]);
            __half2 h0 = __floats2half2_rn(p0.x * sv, p0.y * sv);
            __half2 h1 = __floats2half2_rn(p1.x * sv, p1.y * sv);
            __half2 h2 = __floats2half2_rn(p2.x * sv, p2.y * sv);
            __half2 h3 = __floats2half2_rn(p3.x * sv, p3.y * sv);
            uint4 o;
            o.x = *(unsigned*)&h0; o.y = *(unsigned*)&h1;
            o.z = *(unsigned*)&h2; o.w = *(unsigned*)&h3;
            *(uint4*)(y + (size_t)n * 32 + cg * 8) = o;
        }
    }
}

// ---------------- agg1: gather y1 + LN + ReLU + fused gemm2 -> y2 (fp16) -----
// warp = 4 nodes x 8 lanes, float4 of channels per lane. Exact grid: 800000 thr.
__global__ __launch_bounds__(256) void k_agg1(const __half* __restrict__ y,
                                              __half* __restrict__ y2,
                                              const float* __restrict__ bias,
                                              const float* __restrict__ g,
                                              const float* __restrict__ be,
                                              const float* __restrict__ W2) {
    __shared__ float w2s[32 * 32];
    __shared__ float hsh[8][128];
    int t = threadIdx.x;
    for (int i = t; i < 1024; i += 256) w2s[i] = W2[i];
    __syncthreads();

    int tid  = blockIdx.x * 256 + t;
    int node = tid >> 3;
    int c4   = tid & 7;
    int wid  = t >> 5;
    int ni   = (t >> 3) & 3;

    int lo = d_rowptr[node];
    int hi = d_rowptr[node + 1];

    float4 acc = h4load(y + (size_t)node * 32 + c4 * 4);   // self loop

    int e = lo;
    for (; e + 3 < hi; e += 4) {
        int s0 = __ldg(&d_csr[e + 0]);
        int s1 = __ldg(&d_csr[e + 1]);
        int s2 = __ldg(&d_csr[e + 2]);
        int s3 = __ldg(&d_csr[e + 3]);
        float4 v0 = h4load(y + (size_t)s0 * 32 + c4 * 4);
        float4 v1 = h4load(y + (size_t)s1 * 32 + c4 * 4);
        float4 v2 = h4load(y + (size_t)s2 * 32 + c4 * 4);
        float4 v3 = h4load(y + (size_t)s3 * 32 + c4 * 4);
        acc.x += (v0.x + v1.x) + (v2.x + v3.x);
        acc.y += (v0.y + v1.y) + (v2.y + v3.y);
        acc.z += (v0.z + v1.z) + (v2.z + v3.z);
        acc.w += (v0.w + v1.w) + (v2.w + v3.w);
    }
    for (; e < hi; e++) {
        int s0 = __ldg(&d_csr[e]);
        float4 v0 = h4load(y + (size_t)s0 * 32 + c4 * 4);
        acc.x += v0.x; acc.y += v0.y; acc.z += v0.z; acc.w += v0.w;
    }

    float sv = d_s[node];
    float4 bv = *(const float4*)(bias + c4 * 4);
    acc.x = acc.x * sv + bv.x;
    acc.y = acc.y * sv + bv.y;
    acc.z = acc.z * sv + bv.z;
    acc.w = acc.w * sv + bv.w;

    // LayerNorm over 32 channels (8 lanes x 4)
    float sum = acc.x + acc.y + acc.z + acc.w;
    sum += __shfl_xor_sync(0xffffffffu, sum, 1);
    sum += __shfl_xor_sync(0xffffffffu, sum, 2);
    sum += __shfl_xor_sync(0xffffffffu, sum, 4);
    float mu = sum * (1.0f / 32.0f);
    float dx = acc.x - mu, dy = acc.y - mu, dz = acc.z - mu, dw = acc.w - mu;
    float vs = dx * dx + dy * dy + dz * dz + dw * dw;
    vs += __shfl_xor_sync(0xffffffffu, vs, 1);
    vs += __shfl_xor_sync(0xffffffffu, vs, 2);
    vs += __shfl_xor_sync(0xffffffffu, vs, 4);
    float rinv = rsqrtf(vs * (1.0f / 32.0f) + LN_EPS);

    float4 gv  = *(const float4*)(g  + c4 * 4);
    float4 bev = *(const float4*)(be + c4 * 4);
    // h = relu(LN(...)), then pre-scale by s for next conv: y2 = (s*h) @ W2
    float4 hs;
    hs.x = fmaxf(dx * rinv * gv.x + bev.x, 0.0f) * sv;
    hs.y = fmaxf(dy * rinv * gv.y + bev.y, 0.0f) * sv;
    hs.z = fmaxf(dz * rinv * gv.z + bev.z, 0.0f) * sv;
    hs.w = fmaxf(dw * rinv * gv.w + bev.w, 0.0f) * sv;

    // fused gemm2 (32x32) via smem row exchange
    float* hp = &hsh[wid][ni * 32];
    hp[c4 * 4 + 0] = hs.x; hp[c4 * 4 + 1] = hs.y;
    hp[c4 * 4 + 2] = hs.z; hp[c4 * 4 + 3] = hs.w;
    __syncwarp();

    float hr[32];
    #pragma unroll
    for (int i = 0; i < 8; i++) {
        float4 v = *(float4*)&hsh[wid][ni * 32 + i * 4];
        hr[i * 4 + 0] = v.x; hr[i * 4 + 1] = v.y;
        hr[i * 4 + 2] = v.z; hr[i * 4 + 3] = v.w;
    }
    float o0 = 0.f, o1 = 0.f, o2 = 0.f, o3 = 0.f;
    #pragma unroll
    for (int k = 0; k < 32; k++) {
        float4 wv = *(const float4*)&w2s[k * 32 + c4 * 4];
        o0 += hr[k] * wv.x; o1 += hr[k] * wv.y;
        o2 += hr[k] * wv.z; o3 += hr[k] * wv.w;
    }
    __half2 q0 = __floats2half2_rn(o0, o1);
    __half2 q1 = __floats2half2_rn(o2, o3);
    uint2 ou; ou.x = *(unsigned*)&q0; ou.y = *(unsigned*)&q1;
    *(uint2*)(y2 + (size_t)node * 32 + c4 * 4) = ou;
}

// ---------------- agg2: gather y2 + LN + ReLU + fused gemm3 -> y3 (fp32) -----
__global__ __launch_bounds__(256) void k_agg2f(const __half* __restrict__ y,
                                               float* __restrict__ y3,
                                               const float* __restrict__ bias,
                                               const float* __restrict__ g,
                                               const float* __restrict__ be,
                                               const float* __restrict__ W3) {
    __shared__ float w3s[64];
    int t = threadIdx.x;
    if (t < 64) w3s[t] = W3[t];
    __syncthreads();

    int tid  = blockIdx.x * 256 + t;
    int node = tid >> 3;
    int c4   = tid & 7;

    int lo = d_rowptr[node];
    int hi = d_rowptr[node + 1];

    float4 acc = h4load(y + (size_t)node * 32 + c4 * 4);
    int e = lo;
    for (; e + 3 < hi; e += 4) {
        int s0 = __ldg(&d_csr[e + 0]);
        int s1 = __ldg(&d_csr[e + 1]);
        int s2 = __ldg(&d_csr[e + 2]);
        int s3 = __ldg(&d_csr[e + 3]);
        float4 v0 = h4load(y + (size_t)s0 * 32 + c4 * 4);
        float4 v1 = h4load(y + (size_t)s1 * 32 + c4 * 4);
        float4 v2 = h4load(y + (size_t)s2 * 32 + c4 * 4);
        float4 v3 = h4load(y + (size_t)s3 * 32 + c4 * 4);
        acc.x += (v0.x + v1.x) + (v2.x + v3.x);
        acc.y += (v0.y + v1.y) + (v2.y + v3.y);
        acc.z += (v0.z + v1.z) + (v2.z + v3.z);
        acc.w += (v0.w + v1.w) + (v2.w + v3.w);
    }
    for (; e < hi; e++) {
        int s0 = __ldg(&d_csr[e]);
        float4 v0 = h4load(y + (size_t)s0 * 32 + c4 * 4);
        acc.x += v0.x; acc.y += v0.y; acc.z += v0.z; acc.w += v0.w;
    }

    float sv = d_s[node];
    float4 bv = *(const float4*)(bias + c4 * 4);
    acc.x = acc.x * sv + bv.x;
    acc.y = acc.y * sv + bv.y;
    acc.z = acc.z * sv + bv.z;
    acc.w = acc.w * sv + bv.w;

    float sum = acc.x + acc.y + acc.z + acc.w;
    sum += __shfl_xor_sync(0xffffffffu, sum, 1);
    sum += __shfl_xor_sync(0xffffffffu, sum, 2);
    sum += __shfl_xor_sync(0xffffffffu, sum, 4);
    float mu = sum * (1.0f / 32.0f);
    float dx = acc.x - mu, dy = acc.y - mu, dz = acc.z - mu, dw = acc.w - mu;
    float vs = dx * dx + dy * dy + dz * dz + dw * dw;
    vs += __shfl_xor_sync(0xffffffffu, vs, 1);
    vs += __shfl_xor_sync(0xffffffffu, vs, 2);
    vs += __shfl_xor_sync(0xffffffffu, vs, 4);
    float rinv = rsqrtf(vs * (1.0f / 32.0f) + LN_EPS);

    float4 gv  = *(const float4*)(g  + c4 * 4);
    float4 bev = *(const float4*)(be + c4 * 4);
    float4 hs;
    hs.x = fmaxf(dx * rinv * gv.x + bev.x, 0.0f) * sv;
    hs.y = fmaxf(dy * rinv * gv.y + bev.y, 0.0f) * sv;
    hs.z = fmaxf(dz * rinv * gv.z + bev.z, 0.0f) * sv;
    hs.w = fmaxf(dw * rinv * gv.w + bev.w, 0.0f) * sv;

    // fused gemm3: 32 -> 2, reduce across 8 lanes
    int kb = c4 * 4;
    float a0 = hs.x * w3s[(kb + 0) * 2 + 0] + hs.y * w3s[(kb + 1) * 2 + 0]
             + hs.z * w3s[(kb + 2) * 2 + 0] + hs.w * w3s[(kb + 3) * 2 + 0];
    float a1 = hs.x * w3s[(kb + 0) * 2 + 1] + hs.y * w3s[(kb + 1) * 2 + 1]
             + hs.z * w3s[(kb + 2) * 2 + 1] + hs.w * w3s[(kb + 3) * 2 + 1];
    a0 += __shfl_xor_sync(0xffffffffu, a0, 1);
    a0 += __shfl_xor_sync(0xffffffffu, a0, 2);
    a0 += __shfl_xor_sync(0xffffffffu, a0, 4);
    a1 += __shfl_xor_sync(0xffffffffu, a1, 1);
    a1 += __shfl_xor_sync(0xffffffffu, a1, 2);
    a1 += __shfl_xor_sync(0xffffffffu, a1, 4);
    if (c4 == 0)
        *(float2*)(y3 + (size_t)node * 2) = make_float2(a0, a1);
}

// ---------------- final 2-wide aggregate -> logits ---------------------------
__global__ void k_aggout(const float* __restrict__ y3, float* __restrict__ out,
                         const float* __restrict__ b3) {
    int node = blockIdx.x * blockDim.x + threadIdx.x;
    if (node >= N_NODES) return;

    int lo = d_rowptr[node];
    int hi = d_rowptr[node + 1];

    float2 acc = *(const float2*)(y3 + (size_t)node * 2);
    int e = lo;
    for (; e + 1 < hi; e += 2) {
        int s0 = __ldg(&d_csr[e]);
        int s1 = __ldg(&d_csr[e + 1]);
        float2 v0 = *(const float2*)(y3 + (size_t)s0 * 2);
        float2 v1 = *(const float2*)(y3 + (size_t)s1 * 2);
        acc.x += v0.x + v1.x;
        acc.y += v0.y + v1.y;
    }
    if (e < hi) {
        int s0 = __ldg(&d_csr[e]);
        float2 v0 = *(const float2*)(y3 + (size_t)s0 * 2);
        acc.x += v0.x; acc.y += v0.y;
    }

    float sv = d_s[node];
    float2 r;
    r.x = acc.x * sv + b3[0];
    r.y = acc.y * sv + b3[1];
    *(float2*)(out + (size_t)node * 2) = r;
}

// ---------------- launch -----------------------------------------------------
extern "C" void kernel_launch(void* const* d_in, const int* in_sizes, int n_in,
                              void* d_out, int out_size) {
    const float* x   = (const float*)d_in[0];
    const int*   ei  = (const int*)d_in[1];
    const float* W1  = (const float*)d_in[2];
    const float* b1  = (const float*)d_in[3];
    const float* g1  = (const float*)d_in[4];
    const float* be1 = (const float*)d_in[5];
    const float* W2  = (const float*)d_in[6];
    const float* b2  = (const float*)d_in[7];
    const float* g2  = (const float*)d_in[8];
    const float* be2 = (const float*)d_in[9];
    const float* W3  = (const float*)d_in[10];
    const float* b3  = (const float*)d_in[11];
    float* out = (float*)d_out;

    const int* src = ei;
    const int* dst = ei + N_EDGES;

    __half* y1p; cudaGetSymbolAddress((void**)&y1p, d_y1);
    __half* y2p; cudaGetSymbolAddress((void**)&y2p, d_y2);
    float*  y3p; cudaGetSymbolAddress((void**)&y3p, d_y3);
    int*    cntp; cudaGetSymbolAddress((void**)&cntp, d_cnt);

    const int TB = 256;
    const int gN = (N_NODES + TB - 1) / TB;     // 391
    const int gE = (N_EDGES + TB - 1) / TB;     // 12500
    const int gA = (N_NODES * 8) / TB;          // 3125 (exact)

    // graph preprocessing: degrees, CSR
    cudaMemsetAsync(cntp, 0, N_NODES * sizeof(int));
    k_count<<<gE, TB>>>(dst);
    k_scan_a<<<NB_SCAN, 1024>>>();
    k_scan_b<<<1, 128>>>();
    k_scan_c<<<gN, TB>>>();
    k_fill<<<gE, TB>>>(src, dst);

    // layer 1 GEMM (f32x2), then fused agg+LN+ReLU+gemm2, fused agg+LN+ReLU+gemm3
    k_gemm1<<<gN, 256>>>(x, W1, y1p);
    k_agg1<<<gA, 256>>>(y1p, y2p, b1, g1, be1, W2);
    k_agg2f<<<gA, 256>>>(y2p, y3p, b2, g2, be2, W3);
    k_aggout<<<gN, TB>>>(y3p, out, b3);
}

// round 3
// speedup vs baseline: 1.2549x; 1.1288x over previous
#include <cuda_runtime.h>
#include <cuda_fp16.h>

#define N_NODES 100000
#define N_EDGES 3200000
#define LN_EPS 1e-5f
#define NB_SCAN ((N_NODES + 1023) / 1024)   // 98 scan blocks

typedef unsigned long long ull;

// ---------------- static scratch ---------------------------------------------
__device__ __half d_y1[N_NODES * 32];
__device__ __half d_y2[N_NODES * 32];
__device__ float  d_y3[N_NODES * 2];
__device__ float  d_s[N_NODES];
__device__ int    d_cnt[N_NODES];
__device__ int    d_rowptr[N_NODES + 1];
__device__ int    d_cur[N_NODES];
__device__ int    d_csr[N_EDGES];
__device__ int    d_blocksum[128];
__device__ int    d_blockoff[128];

// ---------------- f32x2 helpers ----------------------------------------------
__device__ __forceinline__ ull pack2(float x) {
    ull r; asm("mov.b64 %0, {%1, %1};" : "=l"(r) : "f"(x)); return r;
}
__device__ __forceinline__ void fma2(ull& d, ull a, ull b) {
    asm("fma.rn.f32x2 %0, %1, %2, %0;" : "+l"(d) : "l"(a), "l"(b));
}
__device__ __forceinline__ float2 unpack2(ull v) {
    float lo, hi; asm("mov.b64 {%0, %1}, %2;" : "=f"(lo), "=f"(hi) : "l"(v));
    return make_float2(lo, hi);
}
__device__ __forceinline__ float4 h4load(const __half* p) {
    uint2 u = *(const uint2*)p;
    __half2 a = *(__half2*)&u.x;
    __half2 b = *(__half2*)&u.y;
    float2 fa = __half22float2(a), fb = __half22float2(b);
    return make_float4(fa.x, fa.y, fb.x, fb.y);
}
__device__ __forceinline__ void acc4(float4& a, float4 v) {
    a.x += v.x; a.y += v.y; a.z += v.z; a.w += v.w;
}

// ---------------- degree count -----------------------------------------------
__global__ void k_count(const int* __restrict__ dst) {
    int e = blockIdx.x * blockDim.x + threadIdx.x;
    if (e < N_EDGES) atomicAdd(&d_cnt[dst[e]], 1);
}

// ---------------- s = rsqrt(deg+1) (parallel branch) -------------------------
__global__ void k_s() {
    int i = blockIdx.x * blockDim.x + threadIdx.x;
    if (i < N_NODES) d_s[i] = rsqrtf((float)d_cnt[i] + 1.0f);
}

// ---------------- warp-shuffle scan ------------------------------------------
__global__ void k_scan_a() {
    __shared__ int wsum[32];
    int t = threadIdx.x, lane = t & 31, w = t >> 5;
    int i = blockIdx.x * 1024 + t;
    int v = (i < N_NODES) ? d_cnt[i] : 0;
    int x = v;
    #pragma unroll
    for (int o = 1; o < 32; o <<= 1) {
        int u = __shfl_up_sync(0xffffffffu, x, o);
        if (lane >= o) x += u;
    }
    if (lane == 31) wsum[w] = x;
    __syncthreads();
    if (w == 0) {
        int y = wsum[lane];
        #pragma unroll
        for (int o = 1; o < 32; o <<= 1) {
            int u = __shfl_up_sync(0xffffffffu, y, o);
            if (lane >= o) y += u;
        }
        wsum[lane] = y;
    }
    __syncthreads();
    int woff = (w == 0) ? 0 : wsum[w - 1];
    if (i < N_NODES) d_rowptr[i] = woff + x - v;          // exclusive
    if (t == 1023) d_blocksum[blockIdx.x] = wsum[31];
}

__global__ void k_scan_b() {
    __shared__ int wsum[4];
    int t = threadIdx.x, lane = t & 31, w = t >> 5;
    int v = (t < NB_SCAN) ? d_blocksum[t] : 0;
    int x = v;
    #pragma unroll
    for (int o = 1; o < 32; o <<= 1) {
        int u = __shfl_up_sync(0xffffffffu, x, o);
        if (lane >= o) x += u;
    }
    if (lane == 31) wsum[w] = x;
    __syncthreads();
    int woff = 0;
    for (int j = 0; j < w; j++) woff += wsum[j];
    if (t < NB_SCAN) d_blockoff[t] = woff + x - v;
}

__global__ void k_scan_c() {
    int i = blockIdx.x * blockDim.x + threadIdx.x;
    if (i < N_NODES) {
        int rp = d_rowptr[i] + d_blockoff[i >> 10];
        d_rowptr[i] = rp;
        d_cur[i]    = rp;
    }
    if (i == 0) d_rowptr[N_NODES] = N_EDGES;
}

__global__ void k_fill(const int* __restrict__ src, const int* __restrict__ dst) {
    int e = blockIdx.x * blockDim.x + threadIdx.x;
    if (e < N_EDGES) {
        int d   = dst[e];
        int pos = atomicAdd(&d_cur[d], 1);
        d_csr[pos] = src[e];
    }
}

// ---------------- gemm1: y1 = fp16( s * (x @ W1) ), 128 -> 32 ----------------
__global__ __launch_bounds__(256) void k_gemm1(const float* __restrict__ x,
                                               const float* __restrict__ W,
                                               __half* __restrict__ y) {
    __shared__ float shw[128 * 32];
    __shared__ float shx[256 * 17];
    int t  = threadIdx.x;
    int cg = t & 3;
    int ng = t >> 2;
    int nb = blockIdx.x * 256;

    for (int i = t; i < 128 * 32; i += 256) shw[i] = W[i];

    ull acc[4][4];
    #pragma unroll
    for (int ni = 0; ni < 4; ni++)
        #pragma unroll
        for (int j = 0; j < 4; j++) acc[ni][j] = 0ull;

    for (int kc = 0; kc < 8; kc++) {
        __syncthreads();
        #pragma unroll
        for (int i = 0; i < 4; i++) {
            int lin = t + i * 256;
            int n = lin >> 2, k4 = lin & 3;
            float4 v = make_float4(0.f, 0.f, 0.f, 0.f);
            if (nb + n < N_NODES)
                v = *(const float4*)(x + (size_t)(nb + n) * 128 + kc * 16 + k4 * 4);
            float* p = &shx[n * 17 + k4 * 4];
            p[0] = v.x; p[1] = v.y; p[2] = v.z; p[3] = v.w;
        }
        __syncthreads();
        #pragma unroll
        for (int k = 0; k < 16; k++) {
            const ull* wp = (const ull*)&shw[(kc * 16 + k) * 32 + cg * 8];
            ull w0 = wp[0], w1 = wp[1], w2 = wp[2], w3 = wp[3];
            #pragma unroll
            for (int ni = 0; ni < 4; ni++) {
                ull a = pack2(shx[(ng * 4 + ni) * 17 + k]);
                fma2(acc[ni][0], a, w0);
                fma2(acc[ni][1], a, w1);
                fma2(acc[ni][2], a, w2);
                fma2(acc[ni][3], a, w3);
            }
        }
    }

    #pragma unroll
    for (int ni = 0; ni < 4; ni++) {
        int n = nb + ng * 4 + ni;
        if (n < N_NODES) {
            float sv = d_s[n];
            float2 p0 = unpack2(acc[ni][0]);
            float2 p1 = unpack2(acc[ni][1]);
            float2 p2 = unpack2(acc[ni][2]);
            float2 p3 = unpack2(acc[ni][3]);
            __half2 h0 = __floats2half2_rn(p0.x * sv, p0.y * sv);
            __half2 h1 = __floats2half2_rn(p1.x * sv, p1.y * sv);
            __half2 h2 = __floats2half2_rn(p2.x * sv, p2.y * sv);
            __half2 h3 = __floats2half2_rn(p3.x * sv, p3.y * sv);
            uint4 o;
            o.x = *(unsigned*)&h0; o.y = *(unsigned*)&h1;
            o.z = *(unsigned*)&h2; o.w = *(unsigned*)&h3;
            *(uint4*)(y + (size_t)n * 32 + cg * 8) = o;
        }
    }
}

// ---------------- agg1: gather + LN + ReLU + fused gemm2 ---------------------
__global__ __launch_bounds__(256) void k_agg1(const __half* __restrict__ y,
                                              __half* __restrict__ y2,
                                              const float* __restrict__ bias,
                                              const float* __restrict__ g,
                                              const float* __restrict__ be,
                                              const float* __restrict__ W2) {
    __shared__ float w2s[32 * 32];
    __shared__ float hsh[8][128];
    int t = threadIdx.x;
    for (int i = t; i < 1024; i += 256) w2s[i] = W2[i];
    __syncthreads();

    int tid  = blockIdx.x * 256 + t;
    int node = tid >> 3;
    int c4   = tid & 7;
    int wid  = t >> 5;
    int ni   = (t >> 3) & 3;

    int lo = d_rowptr[node];
    int hi = d_rowptr[node + 1];

    float4 acc = h4load(y + (size_t)node * 32 + c4 * 4);   // self loop

    int e = lo;
    for (; e + 7 < hi; e += 8) {
        int s0 = __ldg(&d_csr[e + 0]);
        int s1 = __ldg(&d_csr[e + 1]);
        int s2 = __ldg(&d_csr[e + 2]);
        int s3 = __ldg(&d_csr[e + 3]);
        int s4 = __ldg(&d_csr[e + 4]);
        int s5 = __ldg(&d_csr[e + 5]);
        int s6 = __ldg(&d_csr[e + 6]);
        int s7 = __ldg(&d_csr[e + 7]);
        float4 v0 = h4load(y + (size_t)s0 * 32 + c4 * 4);
        float4 v1 = h4load(y + (size_t)s1 * 32 + c4 * 4);
        float4 v2 = h4load(y + (size_t)s2 * 32 + c4 * 4);
        float4 v3 = h4load(y + (size_t)s3 * 32 + c4 * 4);
        float4 v4 = h4load(y + (size_t)s4 * 32 + c4 * 4);
        float4 v5 = h4load(y + (size_t)s5 * 32 + c4 * 4);
        float4 v6 = h4load(y + (size_t)s6 * 32 + c4 * 4);
        float4 v7 = h4load(y + (size_t)s7 * 32 + c4 * 4);
        acc4(acc, v0); acc4(acc, v1); acc4(acc, v2); acc4(acc, v3);
        acc4(acc, v4); acc4(acc, v5); acc4(acc, v6); acc4(acc, v7);
    }
    for (; e + 3 < hi; e += 4) {
        int s0 = __ldg(&d_csr[e + 0]);
        int s1 = __ldg(&d_csr[e + 1]);
        int s2 = __ldg(&d_csr[e + 2]);
        int s3 = __ldg(&d_csr[e + 3]);
        float4 v0 = h4load(y + (size_t)s0 * 32 + c4 * 4);
        float4 v1 = h4load(y + (size_t)s1 * 32 + c4 * 4);
        float4 v2 = h4load(y + (size_t)s2 * 32 + c4 * 4);
        float4 v3 = h4load(y + (size_t)s3 * 32 + c4 * 4);
        acc4(acc, v0); acc4(acc, v1); acc4(acc, v2); acc4(acc, v3);
    }
    for (; e < hi; e++) {
        int s0 = __ldg(&d_csr[e]);
        acc4(acc, h4load(y + (size_t)s0 * 32 + c4 * 4));
    }

    float sv = d_s[node];
    float4 bv = *(const float4*)(bias + c4 * 4);
    acc.x = acc.x * sv + bv.x;
    acc.y = acc.y * sv + bv.y;
    acc.z = acc.z * sv + bv.z;
    acc.w = acc.w * sv + bv.w;

    float sum = acc.x + acc.y + acc.z + acc.w;
    sum += __shfl_xor_sync(0xffffffffu, sum, 1);
    sum += __shfl_xor_sync(0xffffffffu, sum, 2);
    sum += __shfl_xor_sync(0xffffffffu, sum, 4);
    float mu = sum * (1.0f / 32.0f);
    float dx = acc.x - mu, dy = acc.y - mu, dz = acc.z - mu, dw = acc.w - mu;
    float vs = dx * dx + dy * dy + dz * dz + dw * dw;
    vs += __shfl_xor_sync(0xffffffffu, vs, 1);
    vs += __shfl_xor_sync(0xffffffffu, vs, 2);
    vs += __shfl_xor_sync(0xffffffffu, vs, 4);
    float rinv = rsqrtf(vs * (1.0f / 32.0f) + LN_EPS);

    float4 gv  = *(const float4*)(g  + c4 * 4);
    float4 bev = *(const float4*)(be + c4 * 4);
    float4 hs;
    hs.x = fmaxf(dx * rinv * gv.x + bev.x, 0.0f) * sv;
    hs.y = fmaxf(dy * rinv * gv.y + bev.y, 0.0f) * sv;
    hs.z = fmaxf(dz * rinv * gv.z + bev.z, 0.0f) * sv;
    hs.w = fmaxf(dw * rinv * gv.w + bev.w, 0.0f) * sv;

    float* hp = &hsh[wid][ni * 32];
    hp[c4 * 4 + 0] = hs.x; hp[c4 * 4 + 1] = hs.y;
    hp[c4 * 4 + 2] = hs.z; hp[c4 * 4 + 3] = hs.w;
    __syncwarp();

    float hr[32];
    #pragma unroll
    for (int i = 0; i < 8; i++) {
        float4 v = *(float4*)&hsh[wid][ni * 32 + i * 4];
        hr[i * 4 + 0] = v.x; hr[i * 4 + 1] = v.y;
        hr[i * 4 + 2] = v.z; hr[i * 4 + 3] = v.w;
    }
    float o0 = 0.f, o1 = 0.f, o2 = 0.f, o3 = 0.f;
    #pragma unroll
    for (int k = 0; k < 32; k++) {
        float4 wv = *(const float4*)&w2s[k * 32 + c4 * 4];
        o0 += hr[k] * wv.x; o1 += hr[k] * wv.y;
        o2 += hr[k] * wv.z; o3 += hr[k] * wv.w;
    }
    __half2 q0 = __floats2half2_rn(o0, o1);
    __half2 q1 = __floats2half2_rn(o2, o3);
    uint2 ou; ou.x = *(unsigned*)&q0; ou.y = *(unsigned*)&q1;
    *(uint2*)(y2 + (size_t)node * 32 + c4 * 4) = ou;
}

// ---------------- agg2: gather + LN + ReLU + fused gemm3 -> y3 ---------------
__global__ __launch_bounds__(256) void k_agg2f(const __half* __restrict__ y,
                                               float* __restrict__ y3,
                                               const float* __restrict__ bias,
                                               const float* __restrict__ g,
                                               const float* __restrict__ be,
                                               const float* __restrict__ W3) {
    __shared__ float w3s[64];
    int t = threadIdx.x;
    if (t < 64) w3s[t] = W3[t];
    __syncthreads();

    int tid  = blockIdx.x * 256 + t;
    int node = tid >> 3;
    int c4   = tid & 7;

    int lo = d_rowptr[node];
    int hi = d_rowptr[node + 1];

    float4 acc = h4load(y + (size_t)node * 32 + c4 * 4);
    int e = lo;
    for (; e + 7 < hi; e += 8) {
        int s0 = __ldg(&d_csr[e + 0]);
        int s1 = __ldg(&d_csr[e + 1]);
        int s2 = __ldg(&d_csr[e + 2]);
        int s3 = __ldg(&d_csr[e + 3]);
        int s4 = __ldg(&d_csr[e + 4]);
        int s5 = __ldg(&d_csr[e + 5]);
        int s6 = __ldg(&d_csr[e + 6]);
        int s7 = __ldg(&d_csr[e + 7]);
        float4 v0 = h4load(y + (size_t)s0 * 32 + c4 * 4);
        float4 v1 = h4load(y + (size_t)s1 * 32 + c4 * 4);
        float4 v2 = h4load(y + (size_t)s2 * 32 + c4 * 4);
        float4 v3 = h4load(y + (size_t)s3 * 32 + c4 * 4);
        float4 v4 = h4load(y + (size_t)s4 * 32 + c4 * 4);
        float4 v5 = h4load(y + (size_t)s5 * 32 + c4 * 4);
        float4 v6 = h4load(y + (size_t)s6 * 32 + c4 * 4);
        float4 v7 = h4load(y + (size_t)s7 * 32 + c4 * 4);
        acc4(acc, v0); acc4(acc, v1); acc4(acc, v2); acc4(acc, v3);
        acc4(acc, v4); acc4(acc, v5); acc4(acc, v6); acc4(acc, v7);
    }
    for (; e + 3 < hi; e += 4) {
        int s0 = __ldg(&d_csr[e + 0]);
        int s1 = __ldg(&d_csr[e + 1]);
        int s2 = __ldg(&d_csr[e + 2]);
        int s3 = __ldg(&d_csr[e + 3]);
        float4 v0 = h4load(y + (size_t)s0 * 32 + c4 * 4);
        float4 v1 = h4load(y + (size_t)s1 * 32 + c4 * 4);
        float4 v2 = h4load(y + (size_t)s2 * 32 + c4 * 4);
        float4 v3 = h4load(y + (size_t)s3 * 32 + c4 * 4);
        acc4(acc, v0); acc4(acc, v1); acc4(acc, v2); acc4(acc, v3);
    }
    for (; e < hi; e++) {
        int s0 = __ldg(&d_csr[e]);
        acc4(acc, h4load(y + (size_t)s0 * 32 + c4 * 4));
    }

    float sv = d_s[node];
    float4 bv = *(const float4*)(bias + c4 * 4);
    acc.x = acc.x * sv + bv.x;
    acc.y = acc.y * sv + bv.y;
    acc.z = acc.z * sv + bv.z;
    acc.w = acc.w * sv + bv.w;

    float sum = acc.x + acc.y + acc.z + acc.w;
    sum += __shfl_xor_sync(0xffffffffu, sum, 1);
    sum += __shfl_xor_sync(0xffffffffu, sum, 2);
    sum += __shfl_xor_sync(0xffffffffu, sum, 4);
    float mu = sum * (1.0f / 32.0f);
    float dx = acc.x - mu, dy = acc.y - mu, dz = acc.z - mu, dw = acc.w - mu;
    float vs = dx * dx + dy * dy + dz * dz + dw * dw;
    vs += __shfl_xor_sync(0xffffffffu, vs, 1);
    vs += __shfl_xor_sync(0xffffffffu, vs, 2);
    vs += __shfl_xor_sync(0xffffffffu, vs, 4);
    float rinv = rsqrtf(vs * (1.0f / 32.0f) + LN_EPS);

    float4 gv  = *(const float4*)(g  + c4 * 4);
    float4 bev = *(const float4*)(be + c4 * 4);
    float4 hs;
    hs.x = fmaxf(dx * rinv * gv.x + bev.x, 0.0f) * sv;
    hs.y = fmaxf(dy * rinv * gv.y + bev.y, 0.0f) * sv;
    hs.z = fmaxf(dz * rinv * gv.z + bev.z, 0.0f) * sv;
    hs.w = fmaxf(dw * rinv * gv.w + bev.w, 0.0f) * sv;

    int kb = c4 * 4;
    float a0 = hs.x * w3s[(kb + 0) * 2 + 0] + hs.y * w3s[(kb + 1) * 2 + 0]
             + hs.z * w3s[(kb + 2) * 2 + 0] + hs.w * w3s[(kb + 3) * 2 + 0];
    float a1 = hs.x * w3s[(kb + 0) * 2 + 1] + hs.y * w3s[(kb + 1) * 2 + 1]
             + hs.z * w3s[(kb + 2) * 2 + 1] + hs.w * w3s[(kb + 3) * 2 + 1];
    a0 += __shfl_xor_sync(0xffffffffu, a0, 1);
    a0 += __shfl_xor_sync(0xffffffffu, a0, 2);
    a0 += __shfl_xor_sync(0xffffffffu, a0, 4);
    a1 += __shfl_xor_sync(0xffffffffu, a1, 1);
    a1 += __shfl_xor_sync(0xffffffffu, a1, 2);
    a1 += __shfl_xor_sync(0xffffffffu, a1, 4);
    if (c4 == 0)
        *(float2*)(y3 + (size_t)node * 2) = make_float2(a0, a1);
}

// ---------------- final 2-wide aggregate -> logits ---------------------------
__global__ void k_aggout(const float* __restrict__ y3, float* __restrict__ out,
                         const float* __restrict__ b3) {
    int node = blockIdx.x * blockDim.x + threadIdx.x;
    if (node >= N_NODES) return;

    int lo = d_rowptr[node];
    int hi = d_rowptr[node + 1];

    float2 acc = *(const float2*)(y3 + (size_t)node * 2);
    int e = lo;
    for (; e + 3 < hi; e += 4) {
        int s0 = __ldg(&d_csr[e + 0]);
        int s1 = __ldg(&d_csr[e + 1]);
        int s2 = __ldg(&d_csr[e + 2]);
        int s3 = __ldg(&d_csr[e + 3]);
        float2 v0 = *(const float2*)(y3 + (size_t)s0 * 2);
        float2 v1 = *(const float2*)(y3 + (size_t)s1 * 2);
        float2 v2 = *(const float2*)(y3 + (size_t)s2 * 2);
        float2 v3 = *(const float2*)(y3 + (size_t)s3 * 2);
        acc.x += (v0.x + v1.x) + (v2.x + v3.x);
        acc.y += (v0.y + v1.y) + (v2.y + v3.y);
    }
    for (; e < hi; e++) {
        int s0 = __ldg(&d_csr[e]);
        float2 v0 = *(const float2*)(y3 + (size_t)s0 * 2);
        acc.x += v0.x; acc.y += v0.y;
    }

    float sv = d_s[node];
    float2 r;
    r.x = acc.x * sv + b3[0];
    r.y = acc.y * sv + b3[1];
    *(float2*)(out + (size_t)node * 2) = r;
}

// ---------------- launch (fork-join stream capture) --------------------------
extern "C" void kernel_launch(void* const* d_in, const int* in_sizes, int n_in,
                              void* d_out, int out_size) {
    const float* x   = (const float*)d_in[0];
    const int*   ei  = (const int*)d_in[1];
    const float* W1  = (const float*)d_in[2];
    const float* b1  = (const float*)d_in[3];
    const float* g1  = (const float*)d_in[4];
    const float* be1 = (const float*)d_in[5];
    const float* W2  = (const float*)d_in[6];
    const float* b2  = (const float*)d_in[7];
    const float* g2  = (const float*)d_in[8];
    const float* be2 = (const float*)d_in[9];
    const float* W3  = (const float*)d_in[10];
    const float* b3  = (const float*)d_in[11];
    float* out = (float*)d_out;

    const int* src = ei;
    const int* dst = ei + N_EDGES;

    __half* y1p; cudaGetSymbolAddress((void**)&y1p, d_y1);
    __half* y2p; cudaGetSymbolAddress((void**)&y2p, d_y2);
    float*  y3p; cudaGetSymbolAddress((void**)&y3p, d_y3);
    int*    cntp; cudaGetSymbolAddress((void**)&cntp, d_cnt);

    static cudaStream_t s2 = nullptr;
    static cudaEvent_t evFork = nullptr, evJoin = nullptr;
    if (s2 == nullptr) {
        cudaStreamCreateWithFlags(&s2, cudaStreamNonBlocking);
        cudaEventCreateWithFlags(&evFork, cudaEventDisableTiming);
        cudaEventCreateWithFlags(&evJoin, cudaEventDisableTiming);
    }

    const int TB = 256;
    const int gN = (N_NODES + TB - 1) / TB;     // 391
    const int gE = (N_EDGES + TB - 1) / TB;     // 12500
    const int gA = (N_NODES * 8) / TB;          // 3125

    // main chain: degree count then CSR build
    cudaMemsetAsync(cntp, 0, N_NODES * sizeof(int));
    k_count<<<gE, TB>>>(dst);

    // fork: s + gemm1 run concurrently with the scan/fill chain
    cudaEventRecord(evFork, 0);
    cudaStreamWaitEvent(s2, evFork, 0);
    k_s<<<gN, TB, 0, s2>>>();
    k_gemm1<<<gN, 256, 0, s2>>>(x, W1, y1p);
    cudaEventRecord(evJoin, s2);

    k_scan_a<<<NB_SCAN, 1024>>>();
    k_scan_b<<<1, 128>>>();
    k_scan_c<<<gN, TB>>>();
    k_fill<<<gE, TB>>>(src, dst);

    // join: agg1 needs CSR (stream 0) + y1 & s (stream s2)
    cudaStreamWaitEvent(0, evJoin, 0);
    k_agg1<<<gA, 256>>>(y1p, y2p, b1, g1, be1, W2);
    k_agg2f<<<gA, 256>>>(y2p, y3p, b2, g2, be2, W3);
    k_aggout<<<gN, TB>>>(y3p, out, b3);
}